// round 4
// baseline (speedup 1.0000x reference)
#include <cuda_runtime.h>

// Problem constants (fixed by dataset)
#define NN     40000      // nodes
#define NE     640000     // edges
#define DD     128        // feature dim
#define NBATCH 32         // graphs
#define IMGD   4096       // image feature dim
#define AGG_BLOCKS  (NN / 8)      // 5000 (warp per row, 8 warps/block)
#define SCAN_THREADS 1024
#define SCAN_CHUNK   40           // 1024*40 = 40960 >= NN

// ---------------- scratch (static device globals; zero at module load) --------
// Self-restoring invariant: g_hist, g_q, g_sums are zero before every replay;
// each consumer re-zeroes what it read. Everything else is overwritten first.
__device__ int   g_hist[NN];
__device__ float g_dis[NN];
__device__ int   g_off[NN + 1];
__device__ int   g_cur[NN];
__device__ int2  g_e[NE];         // (src, __float_as_int(w)) dst-sorted
__device__ float g_Y[NN * DD];    // dis-scaled features (read-only during agg)
__device__ float g_T[NN * DD];    // aggregation result
__device__ float g_q[NBATCH * IMGD];
__device__ float g_sums[NBATCH * DD];

__device__ __forceinline__ void red_add(float* p, float v) {
    asm volatile("red.global.add.f32 [%0], %1;" :: "l"(p), "f"(v) : "memory");
}

// ---------------- edge histogram (int only) ------------------------------------
__global__ void k_hist(const int* __restrict__ dst) {
    int e = blockIdx.x * blockDim.x + threadIdx.x;
    if (e < NE) atomicAdd(&g_hist[dst[e]], 1);
}

// ---------------- single-kernel exclusive scan (+hist reset) -------------------
__global__ void __launch_bounds__(SCAN_THREADS) k_scan() {
    __shared__ int warp_sums[32];
    int tid = threadIdx.x;
    int lane = tid & 31, wid = tid >> 5;
    int base = tid * SCAN_CHUNK;
    int pref[SCAN_CHUNK];
    int sum = 0;
#pragma unroll
    for (int i = 0; i < SCAN_CHUNK; i++) {
        int idx = base + i;
        int v = 0;
        if (idx < NN) { v = g_hist[idx]; g_hist[idx] = 0; }   // read + reset
        pref[i] = sum;
        sum += v;
    }
    int inc = sum;
#pragma unroll
    for (int o = 1; o < 32; o <<= 1) {
        int t = __shfl_up_sync(0xffffffffu, inc, o);
        if (lane >= o) inc += t;
    }
    if (lane == 31) warp_sums[wid] = inc;
    __syncthreads();
    if (wid == 0) {
        int v = warp_sums[lane];
#pragma unroll
        for (int o = 1; o < 32; o <<= 1) {
            int t = __shfl_up_sync(0xffffffffu, v, o);
            if (lane >= o) v += t;
        }
        warp_sums[lane] = v;
    }
    __syncthreads();
    int thread_base = inc - sum + (wid > 0 ? warp_sums[wid - 1] : 0);
#pragma unroll
    for (int i = 0; i < SCAN_CHUNK; i++) {
        int idx = base + i;
        if (idx < NN) {
            int off = thread_base + pref[i];
            g_off[idx] = off;
            g_cur[idx] = off;
        }
    }
    if (tid == 0) g_off[NN] = NE;
}

// ---------------- scatter edges into dst-sorted int2 records -------------------
__global__ void k_scatter(const int* __restrict__ src, const int* __restrict__ dst,
                          const float* __restrict__ ew) {
    int e = blockIdx.x * blockDim.x + threadIdx.x;
    if (e < NE) {
        int d = dst[e];
        int p = atomicAdd(&g_cur[d], 1);
        g_e[p] = make_int2(src[e], __float_as_int(ew[e]));
    }
}

// ---------------- image GEMM 1: g_q += images @ W_img (split-K) ----------------
// PROFILED LAUNCH (index 3). grid: 32 col-tiles x 8 K-splits.
__global__ void __launch_bounds__(256) k_img1(const float* __restrict__ images,
                                              const float* __restrict__ Wimg) {
    int ct = blockIdx.x & 31;
    int ks = blockIdx.x >> 5;
    int c = threadIdx.x & 31;
    int rg = threadIdx.x >> 5;       // 8 row groups x 4 rows = 32 rows
    int c0 = ct * 128 + c * 4;
    int kbase = ks * 512;
    float acc[4][4] = {};
#pragma unroll 2
    for (int k = kbase; k < kbase + 512; k += 4) {
        float4 a[4];
#pragma unroll
        for (int rr = 0; rr < 4; rr++)
            a[rr] = *(const float4*)&images[(rg * 4 + rr) * IMGD + k];
#pragma unroll
        for (int q = 0; q < 4; q++) {
            float4 w = *(const float4*)&Wimg[(size_t)(k + q) * IMGD + c0];
#pragma unroll
            for (int rr = 0; rr < 4; rr++) {
                float av = (q == 0) ? a[rr].x : (q == 1) ? a[rr].y : (q == 2) ? a[rr].z : a[rr].w;
                acc[rr][0] = fmaf(av, w.x, acc[rr][0]);
                acc[rr][1] = fmaf(av, w.y, acc[rr][1]);
                acc[rr][2] = fmaf(av, w.z, acc[rr][2]);
                acc[rr][3] = fmaf(av, w.w, acc[rr][3]);
            }
        }
    }
#pragma unroll
    for (int rr = 0; rr < 4; rr++) {
        float* p = &g_q[(rg * 4 + rr) * IMGD + c0];
        red_add(p + 0, acc[rr][0]); red_add(p + 1, acc[rr][1]);
        red_add(p + 2, acc[rr][2]); red_add(p + 3, acc[rr][3]);
    }
}

// ---------------- embedding gather + deg (segment sum of sorted w) + dis -------
__global__ void k_gather(const int* __restrict__ ids, const float* __restrict__ emb) {
    int t = blockIdx.x * blockDim.x + threadIdx.x;
    int row = t >> 5, lane = t & 31;
    if (row >= NN) return;
    int j0 = g_off[row], j1 = g_off[row + 1];
    float w = 0.0f;
    for (int j = j0 + lane; j < j1; j += 32) w += __int_as_float(g_e[j].y);
#pragma unroll
    for (int o = 16; o > 0; o >>= 1) w += __shfl_xor_sync(0xffffffffu, w, o);
    float ds = rsqrtf(1.0f + w);    // self-loop weight 1 included
    if (lane == 0) g_dis[row] = ds;
    int id = ids[row];
    float4 v = ((const float4*)emb)[id * (DD / 4) + lane];
    v.x *= ds; v.y *= ds; v.z *= ds; v.w *= ds;
    ((float4*)g_Y)[row * (DD / 4) + lane] = v;
}

// ---------------- aggregation: T[d] = Y[d] + sum_e w_e * Y[src_e] --------------
// warp per destination node; pure gathers (no atomics), edges dst-sorted.
__global__ void __launch_bounds__(256) k_agg() {
    int row = blockIdx.x * 8 + (threadIdx.x >> 5);
    int lane = threadIdx.x & 31;
    const float4* Y4 = (const float4*)g_Y;
    float4 acc0 = Y4[row * 32 + lane];     // self loop (already dis-scaled)
    float4 acc1 = make_float4(0.f, 0.f, 0.f, 0.f);
    int j = g_off[row], end = g_off[row + 1];
    for (; j + 4 <= end; j += 4) {
        int2 e0 = g_e[j], e1 = g_e[j + 1], e2 = g_e[j + 2], e3 = g_e[j + 3];
        float4 v0 = Y4[e0.x * 32 + lane];
        float4 v1 = Y4[e1.x * 32 + lane];
        float4 v2 = Y4[e2.x * 32 + lane];
        float4 v3 = Y4[e3.x * 32 + lane];
        float w0 = __int_as_float(e0.y), w1 = __int_as_float(e1.y);
        float w2 = __int_as_float(e2.y), w3 = __int_as_float(e3.y);
        acc0.x = fmaf(w0, v0.x, acc0.x); acc0.y = fmaf(w0, v0.y, acc0.y);
        acc0.z = fmaf(w0, v0.z, acc0.z); acc0.w = fmaf(w0, v0.w, acc0.w);
        acc1.x = fmaf(w1, v1.x, acc1.x); acc1.y = fmaf(w1, v1.y, acc1.y);
        acc1.z = fmaf(w1, v1.z, acc1.z); acc1.w = fmaf(w1, v1.w, acc1.w);
        acc0.x = fmaf(w2, v2.x, acc0.x); acc0.y = fmaf(w2, v2.y, acc0.y);
        acc0.z = fmaf(w2, v2.z, acc0.z); acc0.w = fmaf(w2, v2.w, acc0.w);
        acc1.x = fmaf(w3, v3.x, acc1.x); acc1.y = fmaf(w3, v3.y, acc1.y);
        acc1.z = fmaf(w3, v3.z, acc1.z); acc1.w = fmaf(w3, v3.w, acc1.w);
    }
    for (; j < end; j++) {
        int2 e = g_e[j];
        float w = __int_as_float(e.y);
        float4 v = Y4[e.x * 32 + lane];
        acc0.x = fmaf(w, v.x, acc0.x); acc0.y = fmaf(w, v.y, acc0.y);
        acc0.z = fmaf(w, v.z, acc0.z); acc0.w = fmaf(w, v.w, acc0.w);
    }
    acc0.x += acc1.x; acc0.y += acc1.y; acc0.z += acc1.z; acc0.w += acc1.w;
    ((float4*)g_T)[row * 32 + lane] = acc0;
}

// ---------------- GCN GEMM: h = (dis o T) @ W + b ------------------------------
// MODE 0: Y = dis * relu(h)   (conv 1, 2)
// MODE 1: pool: g_sums[batch[row]] += h   (conv 3; no store of h)
template <int MODE>
__global__ void __launch_bounds__(256) k_gemm(const float* __restrict__ W,
                                              const float* __restrict__ bias,
                                              const int* __restrict__ batch) {
    __shared__ float As[DD * 32];   // [k][row], 16 KB
    int tid = threadIdx.x;
    int r0 = blockIdx.x * 32;
    const float4* In4 = (const float4*)g_T;
    for (int idx = tid; idx < 1024; idx += 256) {
        int r = idx & 31, kk = idx >> 5;
        float ds = g_dis[r0 + r];
        float4 v = In4[(r0 + r) * 32 + kk];
        As[(kk * 4 + 0) * 32 + r] = v.x * ds;
        As[(kk * 4 + 1) * 32 + r] = v.y * ds;
        As[(kk * 4 + 2) * 32 + r] = v.z * ds;
        As[(kk * 4 + 3) * 32 + r] = v.w * ds;
    }
    __syncthreads();
    int c = tid & 31, rg = tid >> 5;
    const float4* W4 = (const float4*)W;
    const float4* As4 = (const float4*)As;
    float acc[4][4] = {};
#pragma unroll 8
    for (int k = 0; k < DD; k++) {
        float4 a = As4[k * 8 + rg];           // broadcast within warp
        float4 w = __ldg(&W4[k * 32 + c]);    // coalesced
        acc[0][0] = fmaf(a.x, w.x, acc[0][0]); acc[0][1] = fmaf(a.x, w.y, acc[0][1]);
        acc[0][2] = fmaf(a.x, w.z, acc[0][2]); acc[0][3] = fmaf(a.x, w.w, acc[0][3]);
        acc[1][0] = fmaf(a.y, w.x, acc[1][0]); acc[1][1] = fmaf(a.y, w.y, acc[1][1]);
        acc[1][2] = fmaf(a.y, w.z, acc[1][2]); acc[1][3] = fmaf(a.y, w.w, acc[1][3]);
        acc[2][0] = fmaf(a.z, w.x, acc[2][0]); acc[2][1] = fmaf(a.z, w.y, acc[2][1]);
        acc[2][2] = fmaf(a.z, w.z, acc[2][2]); acc[2][3] = fmaf(a.z, w.w, acc[2][3]);
        acc[3][0] = fmaf(a.w, w.x, acc[3][0]); acc[3][1] = fmaf(a.w, w.y, acc[3][1]);
        acc[3][2] = fmaf(a.w, w.z, acc[3][2]); acc[3][3] = fmaf(a.w, w.w, acc[3][3]);
    }
    float4 b4 = ((const float4*)bias)[c];
    if (MODE == 0) {
#pragma unroll
        for (int rr = 0; rr < 4; rr++) {
            int row = r0 + rg * 4 + rr;
            float ds = g_dis[row];
            float4 o = make_float4(fmaxf(acc[rr][0] + b4.x, 0.f) * ds,
                                   fmaxf(acc[rr][1] + b4.y, 0.f) * ds,
                                   fmaxf(acc[rr][2] + b4.z, 0.f) * ds,
                                   fmaxf(acc[rr][3] + b4.w, 0.f) * ds);
            ((float4*)g_Y)[row * 32 + c] = o;
        }
    } else {
        float4 o[4];
#pragma unroll
        for (int rr = 0; rr < 4; rr++)
            o[rr] = make_float4(acc[rr][0] + b4.x, acc[rr][1] + b4.y,
                                acc[rr][2] + b4.z, acc[rr][3] + b4.w);
        int b0 = batch[r0], b31 = batch[r0 + 31];
        if (b0 == b31) {
            // whole block in one graph: smem pre-reduce, 128 atomics/block
            float4 s = make_float4(o[0].x + o[1].x + o[2].x + o[3].x,
                                   o[0].y + o[1].y + o[2].y + o[3].y,
                                   o[0].z + o[1].z + o[2].z + o[3].z,
                                   o[0].w + o[1].w + o[2].w + o[3].w);
            __syncthreads();                   // done reading As; reuse as staging
            float4* sp = (float4*)As;
            sp[rg * 32 + c] = s;
            __syncthreads();
            if (tid < 32) {
                float4 a = sp[tid];
#pragma unroll
                for (int g = 1; g < 8; g++) {
                    float4 t = sp[g * 32 + tid];
                    a.x += t.x; a.y += t.y; a.z += t.z; a.w += t.w;
                }
                float* pp = &g_sums[b0 * DD + tid * 4];
                red_add(pp + 0, a.x); red_add(pp + 1, a.y);
                red_add(pp + 2, a.z); red_add(pp + 3, a.w);
            }
        } else {
#pragma unroll
            for (int rr = 0; rr < 4; rr++) {
                int row = r0 + rg * 4 + rr;
                int bb = batch[row];
                float* pp = &g_sums[bb * DD + c * 4];
                red_add(pp + 0, o[rr].x); red_add(pp + 1, o[rr].y);
                red_add(pp + 2, o[rr].z); red_add(pp + 3, o[rr].w);
            }
        }
    }
}

// ---------------- image head: out = l2norm((q + b_img) @ W_i + b_i) ------------
// Resets g_q row to zero afterwards (self-restoring for next replay).
__global__ void __launch_bounds__(128) k_img2(const float* __restrict__ Wi,
                                              const float* __restrict__ bi,
                                              const float* __restrict__ bimg,
                                              float* __restrict__ out) {
    __shared__ float rbuf[4];
    __shared__ float sinv;
    int m = blockIdx.x, j = threadIdx.x;
    float* qrow = &g_q[m * IMGD];
    float acc[4] = {bi[j], 0.f, 0.f, 0.f};
    for (int k = 0; k < IMGD; k += 16) {
#pragma unroll
        for (int u = 0; u < 4; u++) {
            float4 qv = *(const float4*)&qrow[k + 4 * u];
            float4 bv = *(const float4*)&bimg[k + 4 * u];
            qv.x += bv.x; qv.y += bv.y; qv.z += bv.z; qv.w += bv.w;
            acc[u] = fmaf(qv.x, Wi[(k + 4 * u + 0) * DD + j], acc[u]);
            acc[u] = fmaf(qv.y, Wi[(k + 4 * u + 1) * DD + j], acc[u]);
            acc[u] = fmaf(qv.z, Wi[(k + 4 * u + 2) * DD + j], acc[u]);
            acc[u] = fmaf(qv.w, Wi[(k + 4 * u + 3) * DD + j], acc[u]);
        }
    }
    float a = (acc[0] + acc[1]) + (acc[2] + acc[3]);
    float s = a * a;
#pragma unroll
    for (int o = 16; o > 0; o >>= 1) s += __shfl_xor_sync(0xffffffffu, s, o);
    if ((j & 31) == 0) rbuf[j >> 5] = s;
    __syncthreads();
    if (j == 0) sinv = rsqrtf(rbuf[0] + rbuf[1] + rbuf[2] + rbuf[3]);
    __syncthreads();
    out[m * DD + j] = a * sinv;
    __syncthreads();                       // all reads of qrow done
    for (int k = j; k < IMGD; k += 128) qrow[k] = 0.0f;   // reset for next replay
}

// ---------------- graph head: l2norm(pooled @ W_g + b_g) -----------------------
__global__ void __launch_bounds__(128) k_ghead(const int* __restrict__ batch,
                                               const float* __restrict__ Wg,
                                               const float* __restrict__ bg,
                                               float* __restrict__ out) {
    int b = blockIdx.x, j = threadIdx.x;
    __shared__ float p[DD];
    __shared__ float rbuf[4];
    __shared__ float sinv;
    __shared__ int cnt_s;
    if (j == 0) {
        int lo = 0, hi = NN;                        // lower_bound(batch, b)
        while (lo < hi) { int mid = (lo + hi) >> 1; if (batch[mid] < b) lo = mid + 1; else hi = mid; }
        int lo2 = lo, hi2 = NN;                     // upper_bound(batch, b)
        while (lo2 < hi2) { int mid = (lo2 + hi2) >> 1; if (batch[mid] <= b) lo2 = mid + 1; else hi2 = mid; }
        cnt_s = lo2 - lo;
    }
    __syncthreads();
    float inv = 1.0f / fmaxf((float)cnt_s, 1.0f);
    p[j] = g_sums[b * DD + j] * inv;
    g_sums[b * DD + j] = 0.0f;                      // reset for next replay
    __syncthreads();
    float acc = bg[j];
#pragma unroll 8
    for (int k = 0; k < DD; k++) acc = fmaf(p[k], Wg[k * DD + j], acc);
    float s = acc * acc;
#pragma unroll
    for (int o = 16; o > 0; o >>= 1) s += __shfl_xor_sync(0xffffffffu, s, o);
    if ((j & 31) == 0) rbuf[j >> 5] = s;
    __syncthreads();
    if (j == 0) sinv = rsqrtf(rbuf[0] + rbuf[1] + rbuf[2] + rbuf[3]);
    __syncthreads();
    out[NBATCH * DD + b * DD + j] = acc * sinv;
}

// ---------------- launch --------------------------------------------------------
extern "C" void kernel_launch(void* const* d_in, const int* in_sizes, int n_in,
                              void* d_out, int out_size) {
    const float* images = (const float*)d_in[0];
    const int*   ids    = (const int*)d_in[1];
    const int*   src    = (const int*)d_in[2];
    const int*   dst    = (const int*)d_in[3];
    const float* ew     = (const float*)d_in[4];
    const int*   batch  = (const int*)d_in[5];
    const float* emb    = (const float*)d_in[6];
    const float* W_img  = (const float*)d_in[7];
    const float* b_img  = (const float*)d_in[8];
    const float* W_i    = (const float*)d_in[9];
    const float* b_i    = (const float*)d_in[10];
    const float* W1 = (const float*)d_in[11]; const float* b1 = (const float*)d_in[12];
    const float* W2 = (const float*)d_in[13]; const float* b2 = (const float*)d_in[14];
    const float* W3 = (const float*)d_in[15]; const float* b3 = (const float*)d_in[16];
    const float* W_g = (const float*)d_in[17]; const float* b_g = (const float*)d_in[18];
    float* out = (float*)d_out;

    (void)in_sizes; (void)n_in; (void)out_size;

    k_hist<<<NE / 256, 256>>>(dst);                      // 0
    k_scan<<<1, SCAN_THREADS>>>();                       // 1
    k_scatter<<<NE / 256, 256>>>(src, dst, ew);          // 2
    k_img1<<<256, 256>>>(images, W_img);                 // 3  <- profiled launch
    k_gather<<<AGG_BLOCKS, 256>>>(ids, emb);             // 4

    k_agg<<<AGG_BLOCKS, 256>>>();                        // 5
    k_gemm<0><<<NN / 32, 256>>>(W1, b1, nullptr);        // 6
    k_agg<<<AGG_BLOCKS, 256>>>();                        // 7
    k_gemm<0><<<NN / 32, 256>>>(W2, b2, nullptr);        // 8
    k_agg<<<AGG_BLOCKS, 256>>>();                        // 9
    k_gemm<1><<<NN / 32, 256>>>(W3, b3, batch);          // 10 (+ mean-pool)

    k_img2<<<NBATCH, 128>>>(W_i, b_i, b_img, out);       // 11
    k_ghead<<<NBATCH, 128>>>(batch, W_g, b_g, out);      // 12
}

// round 5
// speedup vs baseline: 1.1416x; 1.1416x over previous
#include <cuda_runtime.h>

// Problem constants (fixed by dataset)
#define NN     40000      // nodes
#define NE     640000     // edges
#define DD     128        // feature dim
#define NBATCH 32         // graphs
#define IMGD   4096       // image feature dim
#define AGG_BLOCKS  (NN / 8)      // 5000 (warp per row, 8 warps/block)
#define SCAN_BLOCKS 157           // ceil(NN/256)
#define IMG_KSPLIT  32            // k_img1 k-splits (1024 blocks total)

// ---------------- scratch (static device globals; zero at module load) --------
// Self-restoring invariant: g_hist, g_q, g_sums are zero before every replay;
// each consumer re-zeroes what it read. Everything else is overwritten first.
__device__ int   g_hist[NN];
__device__ float g_dis[NN];
__device__ int   g_off[NN + 1];
__device__ int   g_cur[NN];
__device__ int   g_bsum[SCAN_BLOCKS];
__device__ int2  g_e[NE];         // (src, __float_as_int(w)) dst-sorted
__device__ float g_Y[NN * DD];    // dis-scaled features (read-only during agg)
__device__ float g_T[NN * DD];    // aggregation result
__device__ float g_q[NBATCH * IMGD];
__device__ float g_sums[NBATCH * DD];

__device__ __forceinline__ void red_add(float* p, float v) {
    asm volatile("red.global.add.f32 [%0], %1;" :: "l"(p), "f"(v) : "memory");
}

// ---------------- edge histogram (int only) ------------------------------------
__global__ void k_hist(const int* __restrict__ dst) {
    int e = blockIdx.x * blockDim.x + threadIdx.x;
    if (e < NE) atomicAdd(&g_hist[dst[e]], 1);
}

// ---------------- 3-kernel exclusive scan (coalesced; hist reset fused) --------
__global__ void k_scan1() {
    __shared__ int s[256];
    int tid = threadIdx.x;
    int i = blockIdx.x * 256 + tid;
    int v = 0;
    if (i < NN) { v = g_hist[i]; g_hist[i] = 0; }   // read + reset (self-restoring)
    s[tid] = v; __syncthreads();
    for (int o = 1; o < 256; o <<= 1) {
        int t = (tid >= o) ? s[tid - o] : 0;
        __syncthreads();
        s[tid] += t;
        __syncthreads();
    }
    if (i < NN) g_off[i] = s[tid] - v;
    if (tid == 255) g_bsum[blockIdx.x] = s[255];
}
__global__ void k_scan2() {
    __shared__ int s[256];
    int tid = threadIdx.x;
    int v = (tid < SCAN_BLOCKS) ? g_bsum[tid] : 0;
    s[tid] = v; __syncthreads();
    for (int o = 1; o < 256; o <<= 1) {
        int t = (tid >= o) ? s[tid - o] : 0;
        __syncthreads();
        s[tid] += t;
        __syncthreads();
    }
    if (tid < SCAN_BLOCKS) g_bsum[tid] = s[tid] - v;
}
__global__ void k_scan3() {
    int i = blockIdx.x * 256 + threadIdx.x;
    if (i < NN) {
        int val = g_off[i] + g_bsum[blockIdx.x];
        g_off[i] = val;
        g_cur[i] = val;
    }
    if (i == 0) g_off[NN] = NE;
}

// ---------------- image GEMM 1: g_q += images @ W_img (deep split-K) -----------
// PROFILED LAUNCH (index 3). grid: 32 col-tiles x 32 K-splits = 1024 blocks.
// Per block: K-chunk of 128, thread tile 4 rows x 4 cols.
__global__ void __launch_bounds__(256) k_img1(const float* __restrict__ images,
                                              const float* __restrict__ Wimg) {
    int ct = blockIdx.x & 31;
    int ks = blockIdx.x >> 5;
    int c = threadIdx.x & 31;
    int rg = threadIdx.x >> 5;       // 8 row groups x 4 rows = 32 rows
    int c0 = ct * 128 + c * 4;
    int kbase = ks * 128;
    float acc[4][4] = {};
#pragma unroll 2
    for (int k = kbase; k < kbase + 128; k += 4) {
        float4 a[4];
#pragma unroll
        for (int rr = 0; rr < 4; rr++)
            a[rr] = *(const float4*)&images[(rg * 4 + rr) * IMGD + k];
#pragma unroll
        for (int q = 0; q < 4; q++) {
            float4 w = *(const float4*)&Wimg[(size_t)(k + q) * IMGD + c0];
#pragma unroll
            for (int rr = 0; rr < 4; rr++) {
                float av = (q == 0) ? a[rr].x : (q == 1) ? a[rr].y : (q == 2) ? a[rr].z : a[rr].w;
                acc[rr][0] = fmaf(av, w.x, acc[rr][0]);
                acc[rr][1] = fmaf(av, w.y, acc[rr][1]);
                acc[rr][2] = fmaf(av, w.z, acc[rr][2]);
                acc[rr][3] = fmaf(av, w.w, acc[rr][3]);
            }
        }
    }
#pragma unroll
    for (int rr = 0; rr < 4; rr++) {
        float* p = &g_q[(rg * 4 + rr) * IMGD + c0];
        red_add(p + 0, acc[rr][0]); red_add(p + 1, acc[rr][1]);
        red_add(p + 2, acc[rr][2]); red_add(p + 3, acc[rr][3]);
    }
}

// ---------------- scatter edges into dst-sorted int2 records -------------------
__global__ void k_scatter(const int* __restrict__ src, const int* __restrict__ dst,
                          const float* __restrict__ ew) {
    int e = blockIdx.x * blockDim.x + threadIdx.x;
    if (e < NE) {
        int d = dst[e];
        int p = atomicAdd(&g_cur[d], 1);
        g_e[p] = make_int2(src[e], __float_as_int(ew[e]));
    }
}

// ---------------- embedding gather + deg (segment sum of sorted w) + dis -------
__global__ void k_gather(const int* __restrict__ ids, const float* __restrict__ emb) {
    int t = blockIdx.x * blockDim.x + threadIdx.x;
    int row = t >> 5, lane = t & 31;
    if (row >= NN) return;
    int j0 = g_off[row], j1 = g_off[row + 1];
    float w = 0.0f;
    for (int j = j0 + lane; j < j1; j += 32) w += __int_as_float(g_e[j].y);
#pragma unroll
    for (int o = 16; o > 0; o >>= 1) w += __shfl_xor_sync(0xffffffffu, w, o);
    float ds = rsqrtf(1.0f + w);    // self-loop weight 1 included
    if (lane == 0) g_dis[row] = ds;
    int id = ids[row];
    float4 v = ((const float4*)emb)[id * (DD / 4) + lane];
    v.x *= ds; v.y *= ds; v.z *= ds; v.w *= ds;
    ((float4*)g_Y)[row * (DD / 4) + lane] = v;
}

// ---------------- aggregation: T[d] = Y[d] + sum_e w_e * Y[src_e] --------------
// warp per destination node; pure gathers (no atomics), edges dst-sorted.
__global__ void __launch_bounds__(256) k_agg() {
    int row = blockIdx.x * 8 + (threadIdx.x >> 5);
    int lane = threadIdx.x & 31;
    const float4* Y4 = (const float4*)g_Y;
    float4 acc0 = Y4[row * 32 + lane];     // self loop (already dis-scaled)
    float4 acc1 = make_float4(0.f, 0.f, 0.f, 0.f);
    int j = g_off[row], end = g_off[row + 1];
    for (; j + 4 <= end; j += 4) {
        int2 e0 = g_e[j], e1 = g_e[j + 1], e2 = g_e[j + 2], e3 = g_e[j + 3];
        float4 v0 = Y4[e0.x * 32 + lane];
        float4 v1 = Y4[e1.x * 32 + lane];
        float4 v2 = Y4[e2.x * 32 + lane];
        float4 v3 = Y4[e3.x * 32 + lane];
        float w0 = __int_as_float(e0.y), w1 = __int_as_float(e1.y);
        float w2 = __int_as_float(e2.y), w3 = __int_as_float(e3.y);
        acc0.x = fmaf(w0, v0.x, acc0.x); acc0.y = fmaf(w0, v0.y, acc0.y);
        acc0.z = fmaf(w0, v0.z, acc0.z); acc0.w = fmaf(w0, v0.w, acc0.w);
        acc1.x = fmaf(w1, v1.x, acc1.x); acc1.y = fmaf(w1, v1.y, acc1.y);
        acc1.z = fmaf(w1, v1.z, acc1.z); acc1.w = fmaf(w1, v1.w, acc1.w);
        acc0.x = fmaf(w2, v2.x, acc0.x); acc0.y = fmaf(w2, v2.y, acc0.y);
        acc0.z = fmaf(w2, v2.z, acc0.z); acc0.w = fmaf(w2, v2.w, acc0.w);
        acc1.x = fmaf(w3, v3.x, acc1.x); acc1.y = fmaf(w3, v3.y, acc1.y);
        acc1.z = fmaf(w3, v3.z, acc1.z); acc1.w = fmaf(w3, v3.w, acc1.w);
    }
    for (; j < end; j++) {
        int2 e = g_e[j];
        float w = __int_as_float(e.y);
        float4 v = Y4[e.x * 32 + lane];
        acc0.x = fmaf(w, v.x, acc0.x); acc0.y = fmaf(w, v.y, acc0.y);
        acc0.z = fmaf(w, v.z, acc0.z); acc0.w = fmaf(w, v.w, acc0.w);
    }
    acc0.x += acc1.x; acc0.y += acc1.y; acc0.z += acc1.z; acc0.w += acc1.w;
    ((float4*)g_T)[row * 32 + lane] = acc0;
}

// ---------------- GCN GEMM: h = (dis o T) @ W + b ------------------------------
// MODE 0: Y = dis * relu(h)   (conv 1, 2)
// MODE 1: pool: g_sums[batch[row]] += h   (conv 3; no store of h)
template <int MODE>
__global__ void __launch_bounds__(256) k_gemm(const float* __restrict__ W,
                                              const float* __restrict__ bias,
                                              const int* __restrict__ batch) {
    __shared__ float As[DD * 32];   // [k][row], 16 KB
    int tid = threadIdx.x;
    int r0 = blockIdx.x * 32;
    const float4* In4 = (const float4*)g_T;
    for (int idx = tid; idx < 1024; idx += 256) {
        int r = idx & 31, kk = idx >> 5;
        float ds = g_dis[r0 + r];
        float4 v = In4[(r0 + r) * 32 + kk];
        As[(kk * 4 + 0) * 32 + r] = v.x * ds;
        As[(kk * 4 + 1) * 32 + r] = v.y * ds;
        As[(kk * 4 + 2) * 32 + r] = v.z * ds;
        As[(kk * 4 + 3) * 32 + r] = v.w * ds;
    }
    __syncthreads();
    int c = tid & 31, rg = tid >> 5;
    const float4* W4 = (const float4*)W;
    const float4* As4 = (const float4*)As;
    float acc[4][4] = {};
#pragma unroll 8
    for (int k = 0; k < DD; k++) {
        float4 a = As4[k * 8 + rg];           // broadcast within warp
        float4 w = __ldg(&W4[k * 32 + c]);    // coalesced; L1-resident after warm
        acc[0][0] = fmaf(a.x, w.x, acc[0][0]); acc[0][1] = fmaf(a.x, w.y, acc[0][1]);
        acc[0][2] = fmaf(a.x, w.z, acc[0][2]); acc[0][3] = fmaf(a.x, w.w, acc[0][3]);
        acc[1][0] = fmaf(a.y, w.x, acc[1][0]); acc[1][1] = fmaf(a.y, w.y, acc[1][1]);
        acc[1][2] = fmaf(a.y, w.z, acc[1][2]); acc[1][3] = fmaf(a.y, w.w, acc[1][3]);
        acc[2][0] = fmaf(a.z, w.x, acc[2][0]); acc[2][1] = fmaf(a.z, w.y, acc[2][1]);
        acc[2][2] = fmaf(a.z, w.z, acc[2][2]); acc[2][3] = fmaf(a.z, w.w, acc[2][3]);
        acc[3][0] = fmaf(a.w, w.x, acc[3][0]); acc[3][1] = fmaf(a.w, w.y, acc[3][1]);
        acc[3][2] = fmaf(a.w, w.z, acc[3][2]); acc[3][3] = fmaf(a.w, w.w, acc[3][3]);
    }
    float4 b4 = ((const float4*)bias)[c];
    if (MODE == 0) {
#pragma unroll
        for (int rr = 0; rr < 4; rr++) {
            int row = r0 + rg * 4 + rr;
            float ds = g_dis[row];
            float4 o = make_float4(fmaxf(acc[rr][0] + b4.x, 0.f) * ds,
                                   fmaxf(acc[rr][1] + b4.y, 0.f) * ds,
                                   fmaxf(acc[rr][2] + b4.z, 0.f) * ds,
                                   fmaxf(acc[rr][3] + b4.w, 0.f) * ds);
            ((float4*)g_Y)[row * 32 + c] = o;
        }
    } else {
        float4 o[4];
#pragma unroll
        for (int rr = 0; rr < 4; rr++)
            o[rr] = make_float4(acc[rr][0] + b4.x, acc[rr][1] + b4.y,
                                acc[rr][2] + b4.z, acc[rr][3] + b4.w);
        int b0 = batch[r0], b31 = batch[r0 + 31];
        if (b0 == b31) {
            // whole block in one graph: smem pre-reduce, 128 atomics/block
            float4 s = make_float4(o[0].x + o[1].x + o[2].x + o[3].x,
                                   o[0].y + o[1].y + o[2].y + o[3].y,
                                   o[0].z + o[1].z + o[2].z + o[3].z,
                                   o[0].w + o[1].w + o[2].w + o[3].w);
            __syncthreads();                   // done reading As; reuse as staging
            float4* sp = (float4*)As;
            sp[rg * 32 + c] = s;
            __syncthreads();
            if (tid < 32) {
                float4 a = sp[tid];
#pragma unroll
                for (int g = 1; g < 8; g++) {
                    float4 t = sp[g * 32 + tid];
                    a.x += t.x; a.y += t.y; a.z += t.z; a.w += t.w;
                }
                float* pp = &g_sums[b0 * DD + tid * 4];
                red_add(pp + 0, a.x); red_add(pp + 1, a.y);
                red_add(pp + 2, a.z); red_add(pp + 3, a.w);
            }
        } else {
#pragma unroll
            for (int rr = 0; rr < 4; rr++) {
                int row = r0 + rg * 4 + rr;
                int bb = batch[row];
                float* pp = &g_sums[bb * DD + c * 4];
                red_add(pp + 0, o[rr].x); red_add(pp + 1, o[rr].y);
                red_add(pp + 2, o[rr].z); red_add(pp + 3, o[rr].w);
            }
        }
    }
}

// ---------------- image head: out = l2norm((q + b_img) @ W_i + b_i) ------------
// Resets g_q row to zero afterwards (self-restoring for next replay).
__global__ void __launch_bounds__(128) k_img2(const float* __restrict__ Wi,
                                              const float* __restrict__ bi,
                                              const float* __restrict__ bimg,
                                              float* __restrict__ out) {
    __shared__ float rbuf[4];
    __shared__ float sinv;
    int m = blockIdx.x, j = threadIdx.x;
    float* qrow = &g_q[m * IMGD];
    float acc[4] = {bi[j], 0.f, 0.f, 0.f};
    for (int k = 0; k < IMGD; k += 16) {
#pragma unroll
        for (int u = 0; u < 4; u++) {
            float4 qv = *(const float4*)&qrow[k + 4 * u];
            float4 bv = *(const float4*)&bimg[k + 4 * u];
            qv.x += bv.x; qv.y += bv.y; qv.z += bv.z; qv.w += bv.w;
            acc[u] = fmaf(qv.x, Wi[(k + 4 * u + 0) * DD + j], acc[u]);
            acc[u] = fmaf(qv.y, Wi[(k + 4 * u + 1) * DD + j], acc[u]);
            acc[u] = fmaf(qv.z, Wi[(k + 4 * u + 2) * DD + j], acc[u]);
            acc[u] = fmaf(qv.w, Wi[(k + 4 * u + 3) * DD + j], acc[u]);
        }
    }
    float a = (acc[0] + acc[1]) + (acc[2] + acc[3]);
    float s = a * a;
#pragma unroll
    for (int o = 16; o > 0; o >>= 1) s += __shfl_xor_sync(0xffffffffu, s, o);
    if ((j & 31) == 0) rbuf[j >> 5] = s;
    __syncthreads();
    if (j == 0) sinv = rsqrtf(rbuf[0] + rbuf[1] + rbuf[2] + rbuf[3]);
    __syncthreads();
    out[m * DD + j] = a * sinv;
    __syncthreads();                       // all reads of qrow done
    for (int k = j; k < IMGD; k += 128) qrow[k] = 0.0f;   // reset for next replay
}

// ---------------- graph head: l2norm(pooled @ W_g + b_g) -----------------------
__global__ void __launch_bounds__(128) k_ghead(const int* __restrict__ batch,
                                               const float* __restrict__ Wg,
                                               const float* __restrict__ bg,
                                               float* __restrict__ out) {
    int b = blockIdx.x, j = threadIdx.x;
    __shared__ float p[DD];
    __shared__ float rbuf[4];
    __shared__ float sinv;
    __shared__ int cnt_s;
    if (j == 0) {
        int lo = 0, hi = NN;                        // lower_bound(batch, b)
        while (lo < hi) { int mid = (lo + hi) >> 1; if (batch[mid] < b) lo = mid + 1; else hi = mid; }
        int lo2 = lo, hi2 = NN;                     // upper_bound(batch, b)
        while (lo2 < hi2) { int mid = (lo2 + hi2) >> 1; if (batch[mid] <= b) lo2 = mid + 1; else hi2 = mid; }
        cnt_s = lo2 - lo;
    }
    __syncthreads();
    float inv = 1.0f / fmaxf((float)cnt_s, 1.0f);
    p[j] = g_sums[b * DD + j] * inv;
    g_sums[b * DD + j] = 0.0f;                      // reset for next replay
    __syncthreads();
    float acc = bg[j];
#pragma unroll 8
    for (int k = 0; k < DD; k++) acc = fmaf(p[k], Wg[k * DD + j], acc);
    float s = acc * acc;
#pragma unroll
    for (int o = 16; o > 0; o >>= 1) s += __shfl_xor_sync(0xffffffffu, s, o);
    if ((j & 31) == 0) rbuf[j >> 5] = s;
    __syncthreads();
    if (j == 0) sinv = rsqrtf(rbuf[0] + rbuf[1] + rbuf[2] + rbuf[3]);
    __syncthreads();
    out[NBATCH * DD + b * DD + j] = acc * sinv;
}

// ---------------- launch --------------------------------------------------------
extern "C" void kernel_launch(void* const* d_in, const int* in_sizes, int n_in,
                              void* d_out, int out_size) {
    const float* images = (const float*)d_in[0];
    const int*   ids    = (const int*)d_in[1];
    const int*   src    = (const int*)d_in[2];
    const int*   dst    = (const int*)d_in[3];
    const float* ew     = (const float*)d_in[4];
    const int*   batch  = (const int*)d_in[5];
    const float* emb    = (const float*)d_in[6];
    const float* W_img  = (const float*)d_in[7];
    const float* b_img  = (const float*)d_in[8];
    const float* W_i    = (const float*)d_in[9];
    const float* b_i    = (const float*)d_in[10];
    const float* W1 = (const float*)d_in[11]; const float* b1 = (const float*)d_in[12];
    const float* W2 = (const float*)d_in[13]; const float* b2 = (const float*)d_in[14];
    const float* W3 = (const float*)d_in[15]; const float* b3 = (const float*)d_in[16];
    const float* W_g = (const float*)d_in[17]; const float* b_g = (const float*)d_in[18];
    float* out = (float*)d_out;

    (void)in_sizes; (void)n_in; (void)out_size;

    k_hist<<<NE / 256, 256>>>(dst);                      // 0
    k_scan1<<<SCAN_BLOCKS, 256>>>();                     // 1
    k_scan2<<<1, 256>>>();                               // 2
    k_img1<<<32 * IMG_KSPLIT, 256>>>(images, W_img);     // 3  <- profiled launch
    k_scan3<<<SCAN_BLOCKS, 256>>>();                     // 4
    k_scatter<<<NE / 256, 256>>>(src, dst, ew);          // 5
    k_gather<<<AGG_BLOCKS, 256>>>(ids, emb);             // 6

    k_agg<<<AGG_BLOCKS, 256>>>();                        // 7
    k_gemm<0><<<NN / 32, 256>>>(W1, b1, nullptr);        // 8
    k_agg<<<AGG_BLOCKS, 256>>>();                        // 9
    k_gemm<0><<<NN / 32, 256>>>(W2, b2, nullptr);        // 10
    k_agg<<<AGG_BLOCKS, 256>>>();                        // 11
    k_gemm<1><<<NN / 32, 256>>>(W3, b3, batch);          // 12 (+ mean-pool)

    k_img2<<<NBATCH, 128>>>(W_i, b_i, b_img, out);       // 13
    k_ghead<<<NBATCH, 128>>>(batch, W_g, b_g, out);      // 14
}